// round 1
// baseline (speedup 1.0000x reference)
#include <cuda_runtime.h>
#include <math.h>

#define IMG   224
#define PSIDE 112
#define P     12544
#define BATCH 32
#define NC    10
#define TILES 49          // 12544 / 256
#define TPB   256

// Scratch (no allocations allowed): parameter trig constants + per-block partial logits.
__device__ float g_consts[14];
__device__ float g_part[BATCH * TILES * NC];

// ---------------------------------------------------------------------------
// Setup: compute trig of the 2x6 circuit parameters once.
// Layout per block of 7: [cos p0, sin p0, cos p1, cos p3, sin p3, cos p4, sin p2*sin p4]
// ---------------------------------------------------------------------------
__global__ void k_setup(const float* __restrict__ rl1, const float* __restrict__ rl2) {
    if (threadIdx.x == 0) {
        const float* prm = rl1;
        float* c = g_consts;
        #pragma unroll
        for (int i = 0; i < 2; i++) {
            c[0] = cosf(prm[0]); c[1] = sinf(prm[0]);
            c[2] = cosf(prm[1]);
            c[3] = cosf(prm[3]); c[4] = sinf(prm[3]);
            c[5] = cosf(prm[4]);
            c[6] = sinf(prm[2]) * sinf(prm[4]);
            prm = rl2; c += 7;
        }
    }
}

// ---------------------------------------------------------------------------
// Closed-form 4-qubit quantum block (circuit factorizes into qubit pairs
// {0,1} and {2,3}; final RZ is a pure phase):
//   Z0 = cos(d0+p0)
//   Z1 = cos(d0+p0) * cos(p1) * cos(d1)
//   Z2 = cos(p4)cos(d2) + sin(p2)sin(p4) * sin(d2) * sin(d3+p3)
//   Z3 = cos(d2) * cos(d3+p3)
// ---------------------------------------------------------------------------
__device__ __forceinline__ void qblock(const float* __restrict__ c,
                                       float d0, float d1, float d2, float d3,
                                       float& z0, float& z1, float& z2, float& z3) {
    float s0, c0; __sincosf(d0, &s0, &c0);
    float cA = c0 * c[0] - s0 * c[1];          // cos(d0 + p0)
    z0 = cA;
    z1 = cA * c[2] * __cosf(d1);
    float s2, c2; __sincosf(d2, &s2, &c2);
    float s3, c3; __sincosf(d3, &s3, &c3);
    float cB = c3 * c[3] - s3 * c[4];          // cos(d3 + p3)
    float sB = s3 * c[3] + c3 * c[4];          // sin(d3 + p3)
    z2 = c[5] * c2 + c[6] * s2 * sB;
    z3 = c2 * cB;
}

// ---------------------------------------------------------------------------
// Main: one thread per (batch, patch). Computes res[4] via two closed-form
// quantum blocks, multiplies into all 10 classes (float4 W row slice),
// block-reduces, writes deterministic per-tile partials.
// ---------------------------------------------------------------------------
__global__ void __launch_bounds__(TPB)
k_main(const float* __restrict__ x, const float* __restrict__ W) {
    const int tile = blockIdx.x;
    const int b    = blockIdx.y;
    const int p    = tile * TPB + threadIdx.x;      // patch index, < 12544
    const int pr   = p / PSIDE;
    const int pc   = p - pr * PSIDE;

    const float* X    = x + b * IMG * IMG;
    const float* row0 = X + (pr * 2) * IMG + pc * 2;
    const float* row1 = row0 + IMG;

    float f0 = row0[0];
    float f1 = row0[1];
    float f2, f3;
    if (pc == PSIDE - 1) { f2 = row1[0]; f3 = row1[1]; }
    else                 { f2 = row0[2]; f3 = row1[0]; }

    float cst[14];
    #pragma unroll
    for (int i = 0; i < 14; i++) cst[i] = g_consts[i];

    float m0, m1, m2, m3;
    qblock(cst, f0, f1, f2, f3, m0, m1, m2, m3);
    float n0, n1, n2, n3;
    qblock(cst + 7, m0, m1, m2, m3, n0, n1, n2, n3);
    const float r0 = m0 + n0, r1 = m1 + n1, r2 = m2 + n2, r3 = m3 + n3;

    // Per-class partial dot products: feature index = 4*p + q  -> one float4/row.
    const float4* __restrict__ W4 = (const float4*)W;
    float acc[NC];
    #pragma unroll
    for (int cc = 0; cc < NC; cc++) {
        float4 w = W4[cc * P + p];
        acc[cc] = fmaf(r0, w.x, fmaf(r1, w.y, fmaf(r2, w.z, r3 * w.w)));
    }

    // Warp reduce each class, then cross-warp via shared.
    #pragma unroll
    for (int cc = 0; cc < NC; cc++) {
        float v = acc[cc];
        #pragma unroll
        for (int off = 16; off > 0; off >>= 1)
            v += __shfl_down_sync(0xffffffffu, v, off);
        acc[cc] = v;
    }

    __shared__ float sm[TPB / 32][NC];
    const int warp = threadIdx.x >> 5;
    const int lane = threadIdx.x & 31;
    if (lane == 0) {
        #pragma unroll
        for (int cc = 0; cc < NC; cc++) sm[warp][cc] = acc[cc];
    }
    __syncthreads();
    if (threadIdx.x < NC) {
        float s = 0.f;
        #pragma unroll
        for (int w = 0; w < TPB / 32; w++) s += sm[w][threadIdx.x];
        g_part[(b * TILES + tile) * NC + threadIdx.x] = s;
    }
}

// ---------------------------------------------------------------------------
// Finalize: per batch, sum the 49 tile partials (fixed order -> deterministic),
// add bias, log-softmax over the 10 classes.
// ---------------------------------------------------------------------------
__global__ void k_final(const float* __restrict__ bias, float* __restrict__ out) {
    const int b = blockIdx.x;
    __shared__ float lg[NC];
    if (threadIdx.x < NC) {
        float s = bias[threadIdx.x];
        const float* pp = g_part + b * TILES * NC + threadIdx.x;
        #pragma unroll 7
        for (int t = 0; t < TILES; t++) s += pp[t * NC];
        lg[threadIdx.x] = s;
    }
    __syncthreads();
    if (threadIdx.x < NC) {
        float mx = lg[0];
        #pragma unroll
        for (int c = 1; c < NC; c++) mx = fmaxf(mx, lg[c]);
        float se = 0.f;
        #pragma unroll
        for (int c = 0; c < NC; c++) se += expf(lg[c] - mx);
        out[b * NC + threadIdx.x] = lg[threadIdx.x] - mx - logf(se);
    }
}

// ---------------------------------------------------------------------------
extern "C" void kernel_launch(void* const* d_in, const int* in_sizes, int n_in,
                              void* d_out, int out_size) {
    const float* x    = (const float*)d_in[0];
    const float* rl1  = (const float*)d_in[1];
    const float* rl2  = (const float*)d_in[2];
    const float* W    = (const float*)d_in[3];
    const float* bias = (const float*)d_in[4];
    float* out        = (float*)d_out;

    k_setup<<<1, 32>>>(rl1, rl2);
    k_main<<<dim3(TILES, BATCH), TPB>>>(x, W);
    k_final<<<BATCH, 32>>>(bias, out);
}

// round 2
// speedup vs baseline: 1.1170x; 1.1170x over previous
#include <cuda_runtime.h>
#include <math.h>

#define IMG    224
#define PSIDE  112
#define P      12544
#define BATCH  32
#define NC     10
#define KP     4                 // patches per thread (consecutive in a row)
#define GB     4                 // batches per thread
#define ROWG   (PSIDE / KP)      // 28 patch-groups per row
#define PG     (P / KP)          // 3136 patch-groups
#define TPB    224               // 7 warps
#define BLKX   (PG / TPB)        // 14
#define NBG    (BATCH / GB)      // 8
#define NBLOCKS (BLKX * NBG)     // 112
#define NWARP  (TPB / 32)

// Scratch (no allocations allowed)
__device__ float    g_part[BATCH * BLKX * NC];
__device__ unsigned g_ctr = 0;

__device__ __forceinline__ float ldcg(const float* p) {
    float v; asm volatile("ld.global.cg.f32 %0, [%1];" : "=f"(v) : "l"(p)); return v;
}

// Closed-form 4-qubit block (circuit factorizes into qubit pairs {0,1},{2,3};
// final RZ is a pure phase):
//   Z0 = cos(d0+p0)
//   Z1 = cos(d0+p0) * cos(p1) * cos(d1)
//   Z2 = cos(p4)cos(d2) + sin(p2)sin(p4) * sin(d2) * sin(d3+p3)
//   Z3 = cos(d2) * cos(d3+p3)
// consts c[7] = {cos p0, sin p0, cos p1, cos p3, sin p3, cos p4, sin p2*sin p4}
__device__ __forceinline__ void qblock(const float c[7],
                                       float d0, float d1, float d2, float d3,
                                       float& z0, float& z1, float& z2, float& z3) {
    float s0, c0; __sincosf(d0, &s0, &c0);
    float cA = c0 * c[0] - s0 * c[1];
    z0 = cA;
    z1 = cA * c[2] * __cosf(d1);
    float s2, c2; __sincosf(d2, &s2, &c2);
    float s3, c3; __sincosf(d3, &s3, &c3);
    float cB = c3 * c[3] - s3 * c[4];
    float sB = s3 * c[3] + c3 * c[4];
    z2 = c[5] * c2 + c[6] * s2 * sB;
    z3 = c2 * cB;
}

__device__ __forceinline__ void make_consts(const float* __restrict__ prm, float c[7]) {
    float s, co;
    __sincosf(__ldg(prm + 0), &s, &co); c[0] = co; c[1] = s;
    c[2] = __cosf(__ldg(prm + 1));
    __sincosf(__ldg(prm + 3), &s, &co); c[3] = co; c[4] = s;
    float s4, c4; __sincosf(__ldg(prm + 4), &s4, &c4);
    c[5] = c4;
    c[6] = __sinf(__ldg(prm + 2)) * s4;
}

__global__ void __launch_bounds__(TPB)
k_fused(const float* __restrict__ x,
        const float* __restrict__ rl1, const float* __restrict__ rl2,
        const float* __restrict__ W,   const float* __restrict__ bias,
        float* __restrict__ out) {
    const int tid  = threadIdx.x;
    const int pg   = blockIdx.x * TPB + tid;       // patch-group [0, 3136)
    const int b0   = blockIdx.y * GB;              // first batch of this group
    const int r    = pg / ROWG;                    // patch row [0, 112)
    const int g    = pg - r * ROWG;                // group in row [0, 28)
    const bool edge = (g == ROWG - 1);

    float c1[7], c2[7];
    make_consts(rl1, c1);
    make_consts(rl2, c2);

    // x loads: row0[0..7] (+row0[8] non-edge), row1[0..7] per batch.
    const float* Xb = x + (size_t)b0 * (IMG * IMG) + (2 * r) * IMG + g * (2 * KP);
    float4 r0a[GB], r0b[GB], r1a[GB], r1b[GB]; float f8[GB];
    #pragma unroll
    for (int q = 0; q < GB; q++) {
        const float* p0 = Xb + q * (IMG * IMG);
        const float* p1 = p0 + IMG;
        r0a[q] = *(const float4*)p0;
        r0b[q] = *(const float4*)(p0 + 4);
        r1a[q] = *(const float4*)p1;
        r1b[q] = *(const float4*)(p1 + 4);
        f8[q]  = edge ? 0.f : __ldg(p0 + 8);
    }

    float acc[GB][NC];
    #pragma unroll
    for (int q = 0; q < GB; q++)
        #pragma unroll
        for (int c = 0; c < NC; c++) acc[q][c] = 0.f;

    const float4* __restrict__ W4 = (const float4*)W;
    const int pbase = r * PSIDE + g * KP;

    #pragma unroll
    for (int i = 0; i < KP; i++) {
        float z0[GB], z1[GB], z2[GB], z3[GB];
        #pragma unroll
        for (int q = 0; q < GB; q++) {
            float f0, f1, f2, f3;
            if      (i == 0) { f0 = r0a[q].x; f1 = r0a[q].y; f2 = r0a[q].z; f3 = r1a[q].x; }
            else if (i == 1) { f0 = r0a[q].z; f1 = r0a[q].w; f2 = r0b[q].x; f3 = r1a[q].z; }
            else if (i == 2) { f0 = r0b[q].x; f1 = r0b[q].y; f2 = r0b[q].z; f3 = r1b[q].x; }
            else {
                f0 = r0b[q].z; f1 = r0b[q].w;
                if (edge) { f2 = r1b[q].z; f3 = r1b[q].w; }
                else      { f2 = f8[q];    f3 = r1b[q].z; }
            }
            float m0, m1, m2, m3, n0, n1, n2, n3;
            qblock(c1, f0, f1, f2, f3, m0, m1, m2, m3);
            qblock(c2, m0, m1, m2, m3, n0, n1, n2, n3);
            z0[q] = m0 + n0; z1[q] = m1 + n1; z2[q] = m2 + n2; z3[q] = m3 + n3;
        }
        const float4* wp = W4 + pbase + i;
        #pragma unroll
        for (int c = 0; c < NC; c++) {
            float4 w = __ldg(wp + c * P);
            #pragma unroll
            for (int q = 0; q < GB; q++)
                acc[q][c] = fmaf(z0[q], w.x, fmaf(z1[q], w.y,
                             fmaf(z2[q], w.z, fmaf(z3[q], w.w, acc[q][c]))));
        }
    }

    // Warp reduce all GB*NC accumulators (over 32 patch-groups per warp).
    #pragma unroll
    for (int q = 0; q < GB; q++)
        #pragma unroll
        for (int c = 0; c < NC; c++) {
            float v = acc[q][c];
            #pragma unroll
            for (int off = 16; off > 0; off >>= 1)
                v += __shfl_down_sync(0xffffffffu, v, off);
            acc[q][c] = v;
        }

    __shared__ float sm[NWARP][GB * NC];
    const int warp = tid >> 5, lane = tid & 31;
    if (lane == 0) {
        #pragma unroll
        for (int q = 0; q < GB; q++)
            #pragma unroll
            for (int c = 0; c < NC; c++) sm[warp][q * NC + c] = acc[q][c];
    }
    __syncthreads();

    if (tid < GB * NC) {
        const int q = tid / NC, c = tid - q * NC;
        float s = 0.f;
        #pragma unroll
        for (int w = 0; w < NWARP; w++) s += sm[w][tid];
        g_part[((b0 + q) * BLKX + blockIdx.x) * NC + c] = s;
    }

    // ---- grid-wide finalize by the last block to finish ----
    __shared__ int lastFlag;
    __threadfence();
    __syncthreads();
    if (tid == 0) lastFlag = (atomicAdd(&g_ctr, 1u) == NBLOCKS - 1);
    __syncthreads();
    if (!lastFlag) return;

    __threadfence();   // acquire: all partials visible
    if (tid < BATCH) {
        float lg[NC];
        #pragma unroll
        for (int c = 0; c < NC; c++) {
            float s = __ldg(bias + c);
            const float* pp = g_part + (tid * BLKX) * NC + c;
            #pragma unroll
            for (int t = 0; t < BLKX; t++) s += ldcg(pp + t * NC);
            lg[c] = s;
        }
        float mx = lg[0];
        #pragma unroll
        for (int c = 1; c < NC; c++) mx = fmaxf(mx, lg[c]);
        float se = 0.f;
        #pragma unroll
        for (int c = 0; c < NC; c++) se += expf(lg[c] - mx);
        const float lse = logf(se);
        #pragma unroll
        for (int c = 0; c < NC; c++) out[tid * NC + c] = lg[c] - mx - lse;
    }
    if (tid == 0) g_ctr = 0;   // reset for next graph replay
}

extern "C" void kernel_launch(void* const* d_in, const int* in_sizes, int n_in,
                              void* d_out, int out_size) {
    const float* x    = (const float*)d_in[0];
    const float* rl1  = (const float*)d_in[1];
    const float* rl2  = (const float*)d_in[2];
    const float* W    = (const float*)d_in[3];
    const float* bias = (const float*)d_in[4];
    float* out        = (float*)d_out;

    k_fused<<<dim3(BLKX, NBG), TPB>>>(x, rl1, rl2, W, bias, out);
}